// round 10
// baseline (speedup 1.0000x reference)
#include <cuda_runtime.h>
#include <cuda_fp16.h>
#include <cstdint>

// Fused VQ forward: fp16 HMMA + margin-gated exact rescoring.
// TWO independent 8-warp groups per CTA (named barriers), each streaming its
// own token tiles — de-phase-locks memory phases from compute phases.
//   inputs [64,1024,64] f32, embedding [512,64] f32
//   out = [loss(1) | quantized_st(65536*64) | perplexity(1) | indices(65536)] f32

#define KN 512
#define DN 64
#define TM 128
#define NTHREADS 512
#define NBLK 148
#define MARGIN_KEYS 900   // ~8.6e-4 in score units (key ulp = 9.537e-7)

// ---- smem layout (bytes) ----
#define AH_OFF0   0            // group0 X fp16 [128 x 128B] SW128
#define AH_OFF1   16384        // group1 X fp16
#define BH_OFF    32768        // E fp16 [512 x 128B] SW128
#define BN_OFF    98304        // [512] f32 ||e||^2 (exact reference chain)
#define NB_OFF    100352       // [512] f32 -(bn+8.5)/2 (acc init)
#define KA_OFF    102400       // [2][128] int chosen code
#define HIST_OFF  103424       // [512] u32
#define CAND_OFF  105472       // [2][8][129] uint2
#define SMEM_TOTAL 121984

#define BARG(g) asm volatile("bar.sync %0, %1;" :: "r"((g) + 1), "r"(256) : "memory")

__device__ double       g_err_sum;
__device__ unsigned int g_counts[KN];
__device__ unsigned int g_done;

__device__ __forceinline__ uint32_t smem_u32(const void* p) {
    uint32_t a;
    asm("{ .reg .u64 t; cvta.to.shared.u64 t, %1; cvt.u32.u64 %0, t; }" : "=r"(a) : "l"(p));
    return a;
}
__device__ __forceinline__ void ldsm4(uint32_t addr, uint32_t* r) {
    asm volatile("ldmatrix.sync.aligned.m8n8.x4.shared.b16 {%0,%1,%2,%3}, [%4];"
                 : "=r"(r[0]), "=r"(r[1]), "=r"(r[2]), "=r"(r[3]) : "r"(addr));
}
__device__ __forceinline__ void mma16816(float* d, const uint32_t* a, const uint32_t* b) {
    asm volatile("mma.sync.aligned.m16n8k16.row.col.f32.f16.f16.f32 "
                 "{%0,%1,%2,%3}, {%4,%5,%6,%7}, {%8,%9}, {%0,%1,%2,%3};"
                 : "+f"(d[0]), "+f"(d[1]), "+f"(d[2]), "+f"(d[3])
                 : "r"(a[0]), "r"(a[1]), "r"(a[2]), "r"(a[3]), "r"(b[0]), "r"(b[1]));
}
__device__ __forceinline__ uint32_t swaddr(uint32_t base, int row, int bc) {
    return base + row * 128 + (bc ^ ((row & 7) << 4));
}
__device__ __forceinline__ uint4 pack8h(const float4 a, const float4 b) {
    __half2 h0 = __floats2half2_rn(a.x, a.y);
    __half2 h1 = __floats2half2_rn(a.z, a.w);
    __half2 h2 = __floats2half2_rn(b.x, b.y);
    __half2 h3 = __floats2half2_rn(b.z, b.w);
    uint4 r;
    r.x = *reinterpret_cast<uint32_t*>(&h0);
    r.y = *reinterpret_cast<uint32_t*>(&h1);
    r.z = *reinterpret_cast<uint32_t*>(&h2);
    r.w = *reinterpret_cast<uint32_t*>(&h3);
    return r;
}

// exact reference-order distance (validated flip-free vs reference)
__device__ __forceinline__ float exact_d(const float* __restrict__ xp,
                                         const float* __restrict__ emb,
                                         float A, float bnk, int k) {
    const float4* ep = (const float4*)(emb + (size_t)k * DN);
    float dot = 0.f;
    #pragma unroll
    for (int i = 0; i < 16; i++) {
        float4 e4 = __ldg(ep + i);
        float4 x4 = __ldg((const float4*)xp + i);
        dot = __fmaf_rn(x4.x, e4.x, dot);
        dot = __fmaf_rn(x4.y, e4.y, dot);
        dot = __fmaf_rn(x4.z, e4.z, dot);
        dot = __fmaf_rn(x4.w, e4.w, dot);
    }
    return __fsub_rn(__fadd_rn(A, bnk), __fmul_rn(2.0f, dot));
}

__global__ void __launch_bounds__(NTHREADS, 1)
vq_all(const float* __restrict__ x, const float* __restrict__ emb,
       float* __restrict__ out, int ntok)
{
    extern __shared__ __align__(1024) char smem[];
    const uint32_t sbase = smem_u32(smem);
    const int tid  = threadIdx.x;
    const int lane = tid & 31;
    const int wid  = tid >> 5;
    const int g    = wid >> 3;          // group 0/1
    const int gwid = wid & 7;           // warp within group
    const int gtid = tid & 255;

    float* out_q    = out + 1;
    float* out_perp = out + 1 + (size_t)ntok * DN;
    float* out_idx  = out + 2 + (size_t)ntok * DN;

    float* bn = (float*)(smem + BN_OFF);
    float* nb = (float*)(smem + NB_OFF);
    int*   ka = (int*)(smem + KA_OFF) + g * TM;
    unsigned int* hist = (unsigned int*)(smem + HIST_OFF);
    uint2* cand = (uint2*)(smem + CAND_OFF) + g * (8 * 129);
    const uint32_t ahs = sbase + (g ? AH_OFF1 : AH_OFF0);

    // ---- once per CTA: E -> fp16 SW128, exact norms, acc-init consts, hist ----
    for (int idx = tid; idx < KN * DN / 8; idx += NTHREADS) {
        int row = idx >> 3;
        int c8  = (idx & 7) * 8;
        const float* gp = emb + (size_t)row * DN + c8;
        float4 f0 = __ldg((const float4*)gp);
        float4 f1 = __ldg((const float4*)gp + 1);
        uint32_t off = (uint32_t)row * 128u + (uint32_t)c8 * 2u;
        uint32_t sw  = off ^ ((off >> 3) & 0x70);
        *(uint4*)(smem + BH_OFF + sw) = pack8h(f0, f1);
    }
    for (int k = tid; k < KN; k += NTHREADS) {
        const float* ep = emb + (size_t)k * DN;
        float s = 0.f;
        #pragma unroll
        for (int i = 0; i < DN; i++) s = __fadd_rn(s, __fmul_rn(ep[i], ep[i]));
        bn[k] = s;
        nb[k] = -0.5f * (s + 8.5f);
        hist[k] = 0u;
    }
    __syncthreads();

    // warp owns 64 codes [gwid*64, gwid*64+64)
    const int wbase = gwid * 64;
    const int r8  = lane & 7;
    const int mat = lane >> 3;
    const int c2  = (lane & 3) * 2;

    // acc-init constants for this thread's 16 code slots
    float nbr[16];
    #pragma unroll
    for (int nf = 0; nf < 8; nf++) {
        nbr[nf * 2]     = nb[wbase + nf * 8 + c2];
        nbr[nf * 2 + 1] = nb[wbase + nf * 8 + c2 + 1];
    }

    // register-cache B fragments (fp16) for 64 codes: bh[ks][16]
    uint32_t bh[4][16];
    #pragma unroll
    for (int ks = 0; ks < 4; ks++) {
        #pragma unroll
        for (int q = 0; q < 4; q++) {
            int row = wbase + q * 16 + (mat >> 1) * 8 + r8;
            int bc  = ks * 32 + (mat & 1) * 16;
            ldsm4(swaddr(sbase + BH_OFF, row, bc), &bh[ks][q * 4]);
        }
    }

    double errd = 0.0;
    const int ntile = ntok / TM;
    const int tstride = 2 * gridDim.x;

    for (int tile = blockIdx.x * 2 + g; tile < ntile; tile += tstride) {
        const int tok0 = tile * TM;

        // ---- convert this group's X tile to fp16 SW128 ----
        for (int idx = gtid; idx < TM * DN / 8; idx += 256) {
            int row = idx >> 3;
            int c8  = (idx & 7) * 8;
            const float* gp = x + (size_t)(tok0 + row) * DN + c8;
            float4 f0 = __ldg((const float4*)gp);
            float4 f1 = __ldg((const float4*)gp + 1);
            uint32_t off = (uint32_t)row * 128u + (uint32_t)c8 * 2u;
            uint32_t sw  = off ^ ((off >> 3) & 0x70);
            *(uint4*)((char*)smem + (g ? AH_OFF1 : AH_OFF0) + sw) = pack8h(f0, f1);
        }
        BARG(g);

        // ---- MMA + select: 8 m-chunks of 16 tokens ----
        #pragma unroll 1
        for (int m = 0; m < 8; m++) {
            // hoist A fragments for all 4 k-steps
            uint32_t af[4][4];
            #pragma unroll
            for (int ks = 0; ks < 4; ks++) {
                int row = m * 16 + (mat & 1) * 8 + r8;
                int bc  = ks * 32 + (mat >> 1) * 16;
                ldsm4(swaddr(ahs, row, bc), af[ks]);
            }

            uint32_t rm1[2] = {0xFFFFFFFFu, 0xFFFFFFFFu};
            uint32_t rm2[2] = {0xFFFFFFFFu, 0xFFFFFFFFu};

            #pragma unroll
            for (int h = 0; h < 2; h++) {          // n-halves: 4 n-frags each
                float acc[16];
                #pragma unroll
                for (int nf2 = 0; nf2 < 4; nf2++) {
                    float v0 = nbr[(h * 4 + nf2) * 2];
                    float v1 = nbr[(h * 4 + nf2) * 2 + 1];
                    acc[nf2*4+0] = v0; acc[nf2*4+1] = v1;
                    acc[nf2*4+2] = v0; acc[nf2*4+3] = v1;
                }
                #pragma unroll
                for (int ks = 0; ks < 4; ks++)
                    #pragma unroll
                    for (int nf2 = 0; nf2 < 4; nf2++)
                        mma16816(&acc[nf2*4], af[ks], &bh[ks][(h*4+nf2)*2]);

                // per token-row: 8 keys -> local top-2 -> merge into running
                #pragma unroll
                for (int half = 0; half < 2; half++) {
                    uint32_t p1[4], p2[4];
                    #pragma unroll
                    for (int nf2 = 0; nf2 < 4; nf2++) {
                        float t0 = __fmul_rn(-2.f, acc[nf2*4 + half*2 + 0]);
                        float t1 = __fmul_rn(-2.f, acc[nf2*4 + half*2 + 1]);
                        uint32_t k0 = (__float_as_uint(t0) << 9)
                                    | (uint32_t)(wbase + (h*4+nf2)*8 + c2);
                        uint32_t k1 = (__float_as_uint(t1) << 9)
                                    | (uint32_t)(wbase + (h*4+nf2)*8 + c2 + 1);
                        p1[nf2] = min(k0, k1); p2[nf2] = max(k0, k1);
                    }
                    uint32_t a1 = min(p1[0], p1[1]);
                    uint32_t a2 = min(max(p1[0], p1[1]), min(p2[0], p2[1]));
                    uint32_t b1 = min(p1[2], p1[3]);
                    uint32_t b2 = min(max(p1[2], p1[3]), min(p2[2], p2[3]));
                    uint32_t l1 = min(a1, b1);
                    uint32_t l2 = min(max(a1, b1), min(a2, b2));
                    uint32_t n1 = min(rm1[half], l1);
                    rm2[half] = min(max(rm1[half], l1), min(rm2[half], l2));
                    rm1[half] = n1;
                }
            }
            // quad shfl reduce + store
            #pragma unroll
            for (int half = 0; half < 2; half++) {
                uint32_t m1 = rm1[half], m2 = rm2[half];
                #pragma unroll
                for (int off = 1; off <= 2; off <<= 1) {
                    uint32_t o1 = __shfl_xor_sync(0xffffffffu, m1, off);
                    uint32_t o2 = __shfl_xor_sync(0xffffffffu, m2, off);
                    uint32_t n1 = min(m1, o1);
                    m2 = min(max(m1, o1), min(m2, o2));
                    m1 = n1;
                }
                if ((lane & 3) == 0) {
                    int tok = m * 16 + half * 8 + (lane >> 2);
                    cand[gwid * 129 + tok] = make_uint2(m1, m2);
                }
            }
        }
        BARG(g);

        // ---- merge + margin gate (+ rare exact rescoring); 2 threads/token ----
        {
            const int tok = gtid >> 1;
            const int ci  = gtid & 1;
            uint32_t p1[4], p2[4];
            #pragma unroll
            for (int w = 0; w < 4; w++) {
                uint2 c = cand[(ci * 4 + w) * 129 + tok];
                p1[w] = c.x; p2[w] = c.y;
            }
            uint32_t a1 = min(p1[0], p1[1]);
            uint32_t a2 = min(max(p1[0], p1[1]), min(p2[0], p2[1]));
            uint32_t b1 = min(p1[2], p1[3]);
            uint32_t b2 = min(max(p1[2], p1[3]), min(p2[2], p2[3]));
            uint32_t m1 = min(a1, b1);
            uint32_t m2 = min(max(a1, b1), min(a2, b2));
            {
                uint32_t o1 = __shfl_xor_sync(0xffffffffu, m1, 1);
                uint32_t o2 = __shfl_xor_sync(0xffffffffu, m2, 1);
                uint32_t n1 = min(m1, o1);
                m2 = min(max(m1, o1), min(m2, o2));
                m1 = n1;
            }
            int gap = (int)(m2 >> 9) - (int)(m1 >> 9);
            int bk;
            if (gap > MARGIN_KEYS) {
                bk = (int)(m1 & 511u);
            } else {
                // rare: top-4 of 16 keys + exact rescoring (redundant per pair, no shfl)
                uint32_t key[16];
                #pragma unroll
                for (int w = 0; w < 8; w++) {
                    uint2 c = cand[w * 129 + tok];
                    key[2*w] = c.x; key[2*w+1] = c.y;
                }
                int kc[4];
                #pragma unroll
                for (int p = 0; p < 4; p++) {
                    uint32_t t8[8];
                    #pragma unroll
                    for (int i = 0; i < 8; i++) t8[i] = min(key[i], key[i + 8]);
                    #pragma unroll
                    for (int i = 0; i < 4; i++) t8[i] = min(t8[i], t8[i + 4]);
                    uint32_t mn = min(min(t8[0], t8[1]), min(t8[2], t8[3]));
                    kc[p] = (int)(mn & 511u);
                    #pragma unroll
                    for (int i = 0; i < 16; i++)
                        if (key[i] == mn) key[i] = 0xFFFFFFFFu;
                }
                const float* xp = x + (size_t)(tok0 + tok) * DN;
                float A = 0.f;   // exact reference-order ||x||^2
                #pragma unroll
                for (int i = 0; i < 16; i++) {
                    float4 x4 = __ldg((const float4*)xp + i);
                    A = __fadd_rn(A, __fmul_rn(x4.x, x4.x));
                    A = __fadd_rn(A, __fmul_rn(x4.y, x4.y));
                    A = __fadd_rn(A, __fmul_rn(x4.z, x4.z));
                    A = __fadd_rn(A, __fmul_rn(x4.w, x4.w));
                }
                float bd = 3e38f; bk = 0x7fffffff;
                #pragma unroll 1
                for (int p = 0; p < 4; p++) {
                    float d = exact_d(xp, emb, A, bn[kc[p]], kc[p]);
                    if (d < bd || (d == bd && kc[p] < bk)) { bd = d; bk = kc[p]; }
                }
            }
            if (ci == 0) {
                ka[tok] = bk;
                out_idx[tok0 + tok] = (float)bk;
                atomicAdd(&hist[bk], 1u);
            }
        }
        BARG(g);

        // ---- gather + straight-through write + err (8 warps x 16 tokens) ----
        float err = 0.f;
        #pragma unroll 4
        for (int t = gwid * 16; t < gwid * 16 + 16; t++) {
            int k = ka[t];
            const float* er = emb + (size_t)k * DN;
            const float* xr = x + (size_t)(tok0 + t) * DN;
            float x0 = __ldg(xr + lane), x1 = __ldg(xr + 32 + lane);
            float q0 = __ldg(er + lane), q1 = __ldg(er + 32 + lane);
            float d0 = __fsub_rn(q0, x0);
            float d1 = __fsub_rn(q1, x1);
            out_q[(size_t)(tok0 + t) * DN + lane]      = __fadd_rn(x0, d0);
            out_q[(size_t)(tok0 + t) * DN + 32 + lane] = __fadd_rn(x1, d1);
            err = __fmaf_rn(d0, d0, __fmaf_rn(d1, d1, err));
        }
        #pragma unroll
        for (int off = 16; off > 0; off >>= 1)
            err += __shfl_xor_sync(0xffffffffu, err, off);
        errd += (double)err;
    }

    // ---- flush per-CTA accumulators ----
    __syncthreads();
    if (lane == 0) atomicAdd(&g_err_sum, errd);
    for (int t = tid; t < KN; t += NTHREADS) {
        unsigned int c = hist[t];
        if (c) atomicAdd(&g_counts[t], c);
    }
    __threadfence();
    __syncthreads();

    // ---- last CTA: loss + perplexity, reset for next graph replay ----
    __shared__ unsigned int s_last;
    __shared__ float s_red[NTHREADS / 32];
    if (tid == 0)
        s_last = (atomicAdd(&g_done, 1u) == (unsigned)(gridDim.x - 1)) ? 1u : 0u;
    __syncthreads();
    if (s_last) {
        float part = 0.f;
        const float invN = 1.0f / (float)ntok;
        for (int k = tid; k < KN; k += NTHREADS) {
            unsigned int c = atomicAdd(&g_counts[k], 0u);
            g_counts[k] = 0u;
            float p = __fmul_rn((float)c, invN);
            part = __fmaf_rn(p, logf(__fadd_rn(p, 1e-10f)), part);
        }
        #pragma unroll
        for (int off = 16; off > 0; off >>= 1)
            part += __shfl_xor_sync(0xffffffffu, part, off);
        if (lane == 0) s_red[wid] = part;
        __syncthreads();
        if (tid == 0) {
            float sum = 0.f;
            #pragma unroll
            for (int w = 0; w < NTHREADS / 32; w++) sum += s_red[w];
            double esum = atomicAdd(&g_err_sum, 0.0);
            float m = (float)(esum / ((double)ntok * (double)DN));
            out[0]      = __fadd_rn(m, __fmul_rn(0.25f, m));
            out_perp[0] = expf(-sum);
            g_err_sum = 0.0;
            g_done = 0u;
        }
    }
}

extern "C" void kernel_launch(void* const* d_in, const int* in_sizes, int n_in,
                              void* d_out, int out_size)
{
    const float* x   = (const float*)d_in[0];
    const float* emb = (const float*)d_in[1];
    const int ntok = in_sizes[0] / DN;   // 65536

    cudaFuncSetAttribute(vq_all, cudaFuncAttributeMaxDynamicSharedMemorySize, SMEM_TOTAL);
    vq_all<<<NBLK, NTHREADS, SMEM_TOTAL>>>(x, emb, (float*)d_out, ntok);
}

// round 12
// speedup vs baseline: 1.1058x; 1.1058x over previous
#include <cuda_runtime.h>
#include <cuda_fp16.h>
#include <cstdint>

// Fused VQ forward: fp16 HMMA + margin-gated exact fp32 rescoring.
// Round-9 structure + acc-bit keys (no FP in select), cp.async X prefetch
// (double-buffered xs), A-fragment hoisting.
//   inputs [64,1024,64] f32, embedding [512,64] f32
//   out = [loss(1) | quantized_st(65536*64) | perplexity(1) | indices(65536)] f32

#define KN 512
#define DN 64
#define TM 128
#define XSTRIDE 68
#define NTHREADS 512
#define NBLK 148
#define MARGIN_KEYS 900   // ~8.6e-4 in score units (key ulp = 9.537e-7)

// ---- smem layout (bytes) ----
#define AH_OFF    0            // [128 x 128B] X fp16 (SW128)
#define BH_OFF    16384        // [512 x 128B] E fp16 (SW128)
#define XS0_OFF   81920        // [128 x 68] f32 staged X, buffer 0
#define XS1_OFF   116736       // buffer 1
#define BN_OFF    151552       // [512] f32 ||e||^2 (exact chain)
#define NB_OFF    153600       // [512] f32 -(bn+8.5)/2
#define KA_OFF    155648       // [128] int
#define HIST_OFF  156160       // [512] u32
#define CAND_OFF  158208       // [16][129] uint2
#define SMEM_TOTAL 174848

__device__ double       g_err_sum;
__device__ unsigned int g_counts[KN];
__device__ unsigned int g_done;

__device__ __forceinline__ uint32_t smem_u32(const void* p) {
    uint32_t a;
    asm("{ .reg .u64 t; cvta.to.shared.u64 t, %1; cvt.u32.u64 %0, t; }" : "=r"(a) : "l"(p));
    return a;
}
__device__ __forceinline__ void ldsm4(uint32_t addr, uint32_t* r) {
    asm volatile("ldmatrix.sync.aligned.m8n8.x4.shared.b16 {%0,%1,%2,%3}, [%4];"
                 : "=r"(r[0]), "=r"(r[1]), "=r"(r[2]), "=r"(r[3]) : "r"(addr));
}
__device__ __forceinline__ void mma16816(float* d, const uint32_t* a, const uint32_t* b) {
    asm volatile("mma.sync.aligned.m16n8k16.row.col.f32.f16.f16.f32 "
                 "{%0,%1,%2,%3}, {%4,%5,%6,%7}, {%8,%9}, {%0,%1,%2,%3};"
                 : "+f"(d[0]), "+f"(d[1]), "+f"(d[2]), "+f"(d[3])
                 : "r"(a[0]), "r"(a[1]), "r"(a[2]), "r"(a[3]), "r"(b[0]), "r"(b[1]));
}
__device__ __forceinline__ uint32_t swaddr(uint32_t base, int row, int bc) {
    return base + row * 128 + (bc ^ ((row & 7) << 4));
}
__device__ __forceinline__ void cp16(uint32_t dst, const void* src) {
    asm volatile("cp.async.ca.shared.global [%0], [%1], 16;" :: "r"(dst), "l"(src) : "memory");
}
#define CP_COMMIT() asm volatile("cp.async.commit_group;" ::: "memory")
#define CP_WAIT0()  asm volatile("cp.async.wait_group 0;" ::: "memory")

__device__ __forceinline__ uint4 pack8h(const float4 a, const float4 b) {
    __half2 h0 = __floats2half2_rn(a.x, a.y);
    __half2 h1 = __floats2half2_rn(a.z, a.w);
    __half2 h2 = __floats2half2_rn(b.x, b.y);
    __half2 h3 = __floats2half2_rn(b.z, b.w);
    uint4 r;
    r.x = *reinterpret_cast<uint32_t*>(&h0);
    r.y = *reinterpret_cast<uint32_t*>(&h1);
    r.z = *reinterpret_cast<uint32_t*>(&h2);
    r.w = *reinterpret_cast<uint32_t*>(&h3);
    return r;
}

// exact reference-order distance (validated flip-free vs reference)
__device__ __forceinline__ float exact_d(const float* __restrict__ xp,
                                         const float* __restrict__ emb,
                                         float A, float bnk, int k) {
    const float4* ep = (const float4*)(emb + (size_t)k * DN);
    float dot = 0.f;
    #pragma unroll
    for (int i = 0; i < 16; i++) {
        float4 e4 = __ldg(ep + i);
        const float4 x4 = *(const float4*)(xp + 4 * i);
        dot = __fmaf_rn(x4.x, e4.x, dot);
        dot = __fmaf_rn(x4.y, e4.y, dot);
        dot = __fmaf_rn(x4.z, e4.z, dot);
        dot = __fmaf_rn(x4.w, e4.w, dot);
    }
    return __fsub_rn(__fadd_rn(A, bnk), __fmul_rn(2.0f, dot));
}

__global__ void __launch_bounds__(NTHREADS, 1)
vq_all(const float* __restrict__ x, const float* __restrict__ emb,
       float* __restrict__ out, int ntok)
{
    extern __shared__ __align__(1024) char smem[];
    const uint32_t sbase = smem_u32(smem);
    const int tid  = threadIdx.x;
    const int lane = tid & 31;
    const int wid  = tid >> 5;

    float* out_q    = out + 1;
    float* out_perp = out + 1 + (size_t)ntok * DN;
    float* out_idx  = out + 2 + (size_t)ntok * DN;

    float* bn = (float*)(smem + BN_OFF);
    float* nb = (float*)(smem + NB_OFF);
    int*   ka = (int*)(smem + KA_OFF);
    unsigned int* hist = (unsigned int*)(smem + HIST_OFF);
    uint2* cand = (uint2*)(smem + CAND_OFF);   // [16][129]

    // ---- once per CTA: E -> fp16 SW128 + norms (exact chain) + hist ----
    for (int idx = tid; idx < KN * DN / 8; idx += NTHREADS) {
        int row = idx >> 3;
        int c8  = (idx & 7) * 8;
        const float* gp = emb + (size_t)row * DN + c8;
        float4 f0 = __ldg((const float4*)gp);
        float4 f1 = __ldg((const float4*)gp + 1);
        uint32_t off = (uint32_t)row * 128u + (uint32_t)c8 * 2u;
        uint32_t sw  = off ^ ((off >> 3) & 0x70);
        *(uint4*)(smem + BH_OFF + sw) = pack8h(f0, f1);
    }
    for (int k = tid; k < KN; k += NTHREADS) {
        const float* ep = emb + (size_t)k * DN;
        float s = 0.f;
        #pragma unroll
        for (int i = 0; i < DN; i++) s = __fadd_rn(s, __fmul_rn(ep[i], ep[i]));
        bn[k] = s;
        nb[k] = -0.5f * (s + 8.5f);
        hist[k] = 0u;
    }

    const int ntile = ntok / TM;

    // ---- prologue: cp.async first X tile into xs[0] ----
    {
        int tile0 = blockIdx.x;
        if (tile0 < ntile) {
            #pragma unroll
            for (int q = 0; q < 4; q++) {
                int idx = tid + q * 512;          // 2048 float4 chunks
                int row = idx >> 4, c4 = (idx & 15) * 4;
                cp16(sbase + XS0_OFF + (row * XSTRIDE + c4) * 4,
                     x + (size_t)(tile0 * TM + row) * DN + c4);
            }
        }
        CP_COMMIT();
        CP_WAIT0();
    }
    __syncthreads();

    const int wbase = wid * 32;
    const int r8  = lane & 7;
    const int mat = lane >> 3;
    const int c2  = (lane & 3) * 2;

    // acc-init constants (fold bn + offset into accumulator)
    float nbr[8];
    #pragma unroll
    for (int nf = 0; nf < 4; nf++) {
        nbr[nf * 2]     = nb[wbase + nf * 8 + c2];
        nbr[nf * 2 + 1] = nb[wbase + nf * 8 + c2 + 1];
    }

    // register-cache B fragments (fp16) for this warp's 32 codes
    uint32_t bh[4][8];
    #pragma unroll
    for (int ks = 0; ks < 4; ks++) {
        #pragma unroll
        for (int q = 0; q < 2; q++) {
            int row = wbase + q * 16 + (mat >> 1) * 8 + r8;
            int bc  = ks * 32 + (mat & 1) * 16;
            ldsm4(swaddr(sbase + BH_OFF, row, bc), &bh[ks][q * 4]);
        }
    }

    double errd = 0.0;
    int buf = 0;

    for (int tile = blockIdx.x; tile < ntile; tile += gridDim.x) {
        const int tok0 = tile * TM;
        float* xs = (float*)(smem + (buf ? XS1_OFF : XS0_OFF));
        const uint32_t xsn = sbase + (buf ? XS0_OFF : XS1_OFF);

        // ---- convert X (from staged smem) to fp16 SW128 ----
        #pragma unroll
        for (int q = 0; q < 2; q++) {
            int idx = tid + q * 512;              // 1024 8-float chunks
            int row = idx >> 3, c8 = (idx & 7) * 8;
            const float* xr = xs + row * XSTRIDE + c8;
            float4 f0 = *(const float4*)xr;
            float4 f1 = *(const float4*)(xr + 4);
            uint32_t off = (uint32_t)row * 128u + (uint32_t)c8 * 2u;
            uint32_t sw  = off ^ ((off >> 3) & 0x70);
            *(uint4*)(smem + AH_OFF + sw) = pack8h(f0, f1);
        }
        // prefetch next tile's X into the other xs buffer (async, no regs)
        {
            int tn = tile + gridDim.x;
            if (tn < ntile) {
                #pragma unroll
                for (int q = 0; q < 4; q++) {
                    int idx = tid + q * 512;
                    int row = idx >> 4, c4 = (idx & 15) * 4;
                    cp16(xsn + (row * XSTRIDE + c4) * 4,
                         x + (size_t)(tn * TM + row) * DN + c4);
                }
            }
            CP_COMMIT();
        }
        __syncthreads();

        // ---- MMA + select: 8 m-chunks of 16 tokens ----
        #pragma unroll 2
        for (int m = 0; m < 8; m++) {
            // hoist A fragments (4 LDSM back-to-back -> MLP)
            uint32_t af[4][4];
            #pragma unroll
            for (int ks = 0; ks < 4; ks++) {
                int row = m * 16 + (mat & 1) * 8 + r8;
                int bc  = ks * 32 + (mat >> 1) * 16;
                ldsm4(swaddr(sbase + AH_OFF, row, bc), af[ks]);
            }

            float acc[16];
            #pragma unroll
            for (int nf = 0; nf < 4; nf++) {
                acc[nf*4+0] = nbr[nf*2];   acc[nf*4+1] = nbr[nf*2+1];
                acc[nf*4+2] = nbr[nf*2];   acc[nf*4+3] = nbr[nf*2+1];
            }
            #pragma unroll
            for (int ks = 0; ks < 4; ks++)
                #pragma unroll
                for (int nf = 0; nf < 4; nf++)
                    mma16816(&acc[nf*4], af[ks], &bh[ks][nf*2]);

            // top-2 via acc-bit keys (acc in (-4.5,-4]: bits monotone in score)
            #pragma unroll
            for (int half = 0; half < 2; half++) {
                uint32_t p1[4], p2[4];
                #pragma unroll
                for (int nf = 0; nf < 4; nf++) {
                    uint32_t k0 = (__float_as_uint(acc[nf*4 + half*2 + 0]) << 9)
                                | (uint32_t)(wbase + nf*8 + c2);
                    uint32_t k1 = (__float_as_uint(acc[nf*4 + half*2 + 1]) << 9)
                                | (uint32_t)(wbase + nf*8 + c2 + 1);
                    p1[nf] = min(k0, k1); p2[nf] = max(k0, k1);
                }
                uint32_t a1 = min(p1[0], p1[1]);
                uint32_t a2 = min(max(p1[0], p1[1]), min(p2[0], p2[1]));
                uint32_t b1 = min(p1[2], p1[3]);
                uint32_t b2 = min(max(p1[2], p1[3]), min(p2[2], p2[3]));
                uint32_t m1 = min(a1, b1);
                uint32_t m2 = min(max(a1, b1), min(a2, b2));
                #pragma unroll
                for (int off = 1; off <= 2; off <<= 1) {
                    uint32_t o1 = __shfl_xor_sync(0xffffffffu, m1, off);
                    uint32_t o2 = __shfl_xor_sync(0xffffffffu, m2, off);
                    uint32_t n1 = min(m1, o1);
                    m2 = min(max(m1, o1), min(m2, o2));
                    m1 = n1;
                }
                if ((lane & 3) == 0) {
                    int tok = m * 16 + half * 8 + (lane >> 2);
                    cand[wid * 129 + tok] = make_uint2(m1, m2);
                }
            }
        }
        __syncthreads();

        // ---- merge: global top-2 + margin gate; rare exact top-4 rescore ----
        {
            const int tok = tid >> 2;
            const int ci  = tid & 3;
            const uint32_t qmask = 0xFu << (lane & 28);

            uint32_t p1[4], p2[4];
            #pragma unroll
            for (int w = 0; w < 4; w++) {
                uint2 c = cand[(ci * 4 + w) * 129 + tok];
                p1[w] = c.x; p2[w] = c.y;
            }
            uint32_t a1 = min(p1[0], p1[1]);
            uint32_t a2 = min(max(p1[0], p1[1]), min(p2[0], p2[1]));
            uint32_t b1 = min(p1[2], p1[3]);
            uint32_t b2 = min(max(p1[2], p1[3]), min(p2[2], p2[3]));
            uint32_t m1 = min(a1, b1);
            uint32_t m2 = min(max(a1, b1), min(a2, b2));
            #pragma unroll
            for (int off = 1; off <= 2; off <<= 1) {
                uint32_t o1 = __shfl_xor_sync(0xffffffffu, m1, off);
                uint32_t o2 = __shfl_xor_sync(0xffffffffu, m2, off);
                uint32_t n1 = min(m1, o1);
                m2 = min(max(m1, o1), min(m2, o2));
                m1 = n1;
            }
            int gap = (int)(m2 >> 9) - (int)(m1 >> 9);
            int bk;
            if (gap > MARGIN_KEYS) {
                bk = (int)(m1 & 511u);       // provably the reference argmin
            } else {
                uint32_t key[32];
                #pragma unroll
                for (int w = 0; w < 16; w++) {
                    uint2 c = cand[w * 129 + tok];
                    key[2*w] = c.x; key[2*w+1] = c.y;
                }
                int kc = 0;
                #pragma unroll
                for (int p = 0; p < 4; p++) {
                    uint32_t t16[16];
                    #pragma unroll
                    for (int i = 0; i < 16; i++) t16[i] = min(key[i], key[i + 16]);
                    #pragma unroll
                    for (int i = 0; i < 8; i++) t16[i] = min(t16[i], t16[i + 8]);
                    #pragma unroll
                    for (int i = 0; i < 4; i++) t16[i] = min(t16[i], t16[i + 4]);
                    uint32_t mn = min(min(t16[0], t16[1]), min(t16[2], t16[3]));
                    if (p == ci) kc = (int)(mn & 511u);
                    #pragma unroll
                    for (int i = 0; i < 32; i++)
                        if (key[i] == mn) key[i] = 0xFFFFFFFFu;
                }
                const float* xp = xs + tok * XSTRIDE;
                float A = 0.f;   // exact reference-order ||x||^2
                #pragma unroll
                for (int i = 0; i < DN; i++) A = __fadd_rn(A, __fmul_rn(xp[i], xp[i]));
                float bd = exact_d(xp, emb, A, bn[kc], kc);
                bk = kc;
                #pragma unroll
                for (int off = 1; off <= 2; off <<= 1) {
                    float od = __shfl_xor_sync(qmask, bd, off);
                    int   ok = __shfl_xor_sync(qmask, bk, off);
                    if (od < bd || (od == bd && ok < bk)) { bd = od; bk = ok; }
                }
            }
            if (ci == 0) {
                ka[tok] = bk;
                out_idx[tok0 + tok] = (float)bk;
                atomicAdd(&hist[bk], 1u);
            }
        }
        __syncthreads();

        // ---- gather + straight-through write + err (16 warps x 8 tokens) ----
        float err = 0.f;
        #pragma unroll 2
        for (int t = wid * 8; t < wid * 8 + 8; t++) {
            int k = ka[t];
            const float* er = emb + (size_t)k * DN;
            const float* xr = xs + t * XSTRIDE;
            float x0 = xr[lane], x1 = xr[32 + lane];
            float q0 = __ldg(er + lane), q1 = __ldg(er + 32 + lane);
            float d0 = __fsub_rn(q0, x0);
            float d1 = __fsub_rn(q1, x1);
            out_q[(size_t)(tok0 + t) * DN + lane]      = __fadd_rn(x0, d0);
            out_q[(size_t)(tok0 + t) * DN + 32 + lane] = __fadd_rn(x1, d1);
            err = __fmaf_rn(d0, d0, __fmaf_rn(d1, d1, err));
        }
        #pragma unroll
        for (int off = 16; off > 0; off >>= 1)
            err += __shfl_xor_sync(0xffffffffu, err, off);
        errd += (double)err;

        CP_WAIT0();          // next xs buffer landed
        __syncthreads();
        buf ^= 1;
    }

    // ---- flush per-CTA accumulators ----
    if (lane == 0) atomicAdd(&g_err_sum, errd);
    for (int t = tid; t < KN; t += NTHREADS) {
        unsigned int c = hist[t];
        if (c) atomicAdd(&g_counts[t], c);
    }
    __threadfence();
    __syncthreads();

    // ---- last CTA: loss + perplexity, reset for next graph replay ----
    __shared__ unsigned int s_last;
    __shared__ float s_red[NTHREADS / 32];
    if (tid == 0)
        s_last = (atomicAdd(&g_done, 1u) == (unsigned)(gridDim.x - 1)) ? 1u : 0u;
    __syncthreads();
    if (s_last) {
        float part = 0.f;
        const float invN = 1.0f / (float)ntok;
        for (int k = tid; k < KN; k += NTHREADS) {
            unsigned int c = atomicAdd(&g_counts[k], 0u);
            g_counts[k] = 0u;
            float p = __fmul_rn((float)c, invN);
            part = __fmaf_rn(p, logf(__fadd_rn(p, 1e-10f)), part);
        }
        #pragma unroll
        for (int off = 16; off > 0; off >>= 1)
            part += __shfl_xor_sync(0xffffffffu, part, off);
        if (lane == 0) s_red[wid] = part;
        __syncthreads();
        if (tid == 0) {
            float sum = 0.f;
            #pragma unroll
            for (int w = 0; w < NTHREADS / 32; w++) sum += s_red[w];
            double esum = atomicAdd(&g_err_sum, 0.0);
            float m = (float)(esum / ((double)ntok * (double)DN));
            out[0]      = __fadd_rn(m, __fmul_rn(0.25f, m));
            out_perp[0] = expf(-sum);
            g_err_sum = 0.0;
            g_done = 0u;
        }
    }
}

extern "C" void kernel_launch(void* const* d_in, const int* in_sizes, int n_in,
                              void* d_out, int out_size)
{
    const float* x   = (const float*)d_in[0];
    const float* emb = (const float*)d_in[1];
    const int ntok = in_sizes[0] / DN;   // 65536

    cudaFuncSetAttribute(vq_all, cudaFuncAttributeMaxDynamicSharedMemorySize, SMEM_TOTAL);
    vq_all<<<NBLK, NTHREADS, SMEM_TOTAL>>>(x, emb, (float*)d_out, ntok);
}